// round 1
// baseline (speedup 1.0000x reference)
#include <cuda_runtime.h>
#include <cstdint>

#define S_LEN   4096
#define HID_    2880
#define H_Q_    64
#define H_KV_   8
#define G_      8
#define D_      64
#define HALF_   32
#define W_      128
#define NB_     32              // S/W
#define QKV_OUT 5120            // (H_Q + 2*H_KV) * D
#define ATTN_W  4096            // H_Q * D

// ---------------------------------------------------------------------------
// Scratch (static device arrays — no allocation in kernel_launch)
// ---------------------------------------------------------------------------
__device__ float g_qkv[(size_t)S_LEN * QKV_OUT];   // qkv projection output
__device__ float g_attn[(size_t)S_LEN * ATTN_W];   // attention output

__device__ __forceinline__ unsigned f2tf(float x) {
    unsigned r;
    asm("cvt.rna.tf32.f32 %0, %1;" : "=r"(r) : "f"(x));
    return r;
}

#define MMA_TF32(d, a, b)                                                     \
    asm volatile(                                                             \
        "mma.sync.aligned.m16n8k8.row.col.f32.tf32.tf32.f32 "                 \
        "{%0,%1,%2,%3}, {%4,%5,%6,%7}, {%8,%9}, {%0,%1,%2,%3};\n"             \
        : "+f"((d)[0]), "+f"((d)[1]), "+f"((d)[2]), "+f"((d)[3])              \
        : "r"((a)[0]), "r"((a)[1]), "r"((a)[2]), "r"((a)[3]),                 \
          "r"((b)[0]), "r"((b)[1]))

// ---------------------------------------------------------------------------
// TF32 GEMM:  C[M,N] = A[M,K] @ B[K,N] + bias[N]
// A, B row-major fp32 in gmem (converted to tf32 on smem store).
// M % 128 == 0, K % 16 == 0; N arbitrary (guarded).
// CTA tile 128x128, k-step 16, 8 warps as 4(M) x 2(N), warp tile 32x64.
// ---------------------------------------------------------------------------
__global__ void __launch_bounds__(256, 2)
gemm_tf32(const float* __restrict__ A, const float* __restrict__ B,
          const float* __restrict__ bias, float* __restrict__ C,
          int M, int N, int K)
{
    __shared__ float As[2][128 * 20];   // [row][k], stride 20 (pad 4) -> conflict-free frags
    __shared__ float Bs[2][16 * 136];   // [k][n],  stride 136 (pad 8) -> conflict-free frags

    const int tid  = threadIdx.x;
    const int m0   = blockIdx.y * 128;
    const int n0   = blockIdx.x * 128;
    const int warp = tid >> 5;
    const int lane = tid & 31;
    const int wm   = (warp & 3) << 5;   // 0,32,64,96
    const int wn   = (warp >> 2) << 6;  // 0,64
    const int ly   = lane >> 2;         // groupID  (0..7)
    const int lx   = lane & 3;          // thread-in-group (0..3)

    float acc[2][8][4];
#pragma unroll
    for (int a = 0; a < 2; a++)
#pragma unroll
        for (int b2 = 0; b2 < 8; b2++)
#pragma unroll
            for (int c = 0; c < 4; c++) acc[a][b2][c] = 0.f;

    float4 pa[2];
    float  pb[8];

    const int nK = K >> 4;

    auto ldg_tile = [&](int kt) {
        const int k0 = kt << 4;
#pragma unroll
        for (int j = 0; j < 2; j++) {
            int f = tid + (j << 8);
            int r = f >> 2, c4 = f & 3;
            pa[j] = *reinterpret_cast<const float4*>(
                A + (size_t)(m0 + r) * K + k0 + (c4 << 2));
        }
#pragma unroll
        for (int j = 0; j < 8; j++) {
            int idx = tid + (j << 8);
            int kk = idx >> 7, nn = idx & 127;
            int col = n0 + nn;
            pb[j] = (col < N) ? B[(size_t)(k0 + kk) * N + col] : 0.f;
        }
    };
    auto sts_tile = [&](int buf) {
#pragma unroll
        for (int j = 0; j < 2; j++) {
            int f = tid + (j << 8);
            int r = f >> 2, c4 = f & 3;
            float* p = &As[buf][r * 20 + (c4 << 2)];
            p[0] = __uint_as_float(f2tf(pa[j].x));
            p[1] = __uint_as_float(f2tf(pa[j].y));
            p[2] = __uint_as_float(f2tf(pa[j].z));
            p[3] = __uint_as_float(f2tf(pa[j].w));
        }
#pragma unroll
        for (int j = 0; j < 8; j++) {
            int idx = tid + (j << 8);
            int kk = idx >> 7, nn = idx & 127;
            Bs[buf][kk * 136 + nn] = __uint_as_float(f2tf(pb[j]));
        }
    };

    ldg_tile(0);
    sts_tile(0);
    __syncthreads();

    for (int t = 0; t < nK; t++) {
        const int cur = t & 1;
        if (t + 1 < nK) ldg_tile(t + 1);

        const float* as = As[cur];
        const float* bs = Bs[cur];
#pragma unroll
        for (int s = 0; s < 2; s++) {
            const int kb = s << 3;
            unsigned af[2][4];
#pragma unroll
            for (int mt = 0; mt < 2; mt++) {
                int r = wm + (mt << 4) + ly;
                af[mt][0] = __float_as_uint(as[r * 20 + kb + lx]);
                af[mt][1] = __float_as_uint(as[(r + 8) * 20 + kb + lx]);
                af[mt][2] = __float_as_uint(as[r * 20 + kb + lx + 4]);
                af[mt][3] = __float_as_uint(as[(r + 8) * 20 + kb + lx + 4]);
            }
#pragma unroll
            for (int nt = 0; nt < 8; nt++) {
                int col = wn + (nt << 3) + ly;
                unsigned bf[2];
                bf[0] = __float_as_uint(bs[(kb + lx) * 136 + col]);
                bf[1] = __float_as_uint(bs[(kb + lx + 4) * 136 + col]);
#pragma unroll
                for (int mt = 0; mt < 2; mt++) MMA_TF32(acc[mt][nt], af[mt], bf);
            }
        }
        if (t + 1 < nK) sts_tile((t + 1) & 1);
        __syncthreads();
    }

    // epilogue: C = acc + bias
#pragma unroll
    for (int mt = 0; mt < 2; mt++) {
        const int r0 = m0 + wm + (mt << 4) + ly;
#pragma unroll
        for (int nt = 0; nt < 8; nt++) {
            const int c = n0 + wn + (nt << 3) + (lx << 1);
            if (c < N) {
                float bz = bias[c];
                C[(size_t)r0 * N + c]       = acc[mt][nt][0] + bz;
                C[(size_t)(r0 + 8) * N + c] = acc[mt][nt][2] + bz;
                if (c + 1 < N) {
                    float b1 = bias[c + 1];
                    C[(size_t)r0 * N + c + 1]       = acc[mt][nt][1] + b1;
                    C[(size_t)(r0 + 8) * N + c + 1] = acc[mt][nt][3] + b1;
                }
            }
        }
    }
}

// ---------------------------------------------------------------------------
// RoPE (neox), in-place on q (heads 0..63) and k (heads 64..71) of g_qkv
// ---------------------------------------------------------------------------
__global__ void rope_kernel(float* __restrict__ qkv,
                            const float* __restrict__ cosb,
                            const float* __restrict__ sinb)
{
    const int idx = blockIdx.x * blockDim.x + threadIdx.x;
    const int total = S_LEN * 72 * HALF_;
    if (idx >= total) return;
    const int d = idx & 31;
    const int h = (idx >> 5) % 72;          // 0..63 q heads, 64..71 k heads
    const int s = idx / (72 * 32);
    const size_t base = (size_t)s * QKV_OUT + h * 64;   // q & k are contiguous
    const float x1 = qkv[base + d];
    const float x2 = qkv[base + d + 32];
    const float c  = cosb[s * 32 + d];
    const float sn = sinb[s * 32 + d];
    qkv[base + d]      = x1 * c - x2 * sn;
    qkv[base + d + 32] = x2 * c + x1 * sn;
}

// ---------------------------------------------------------------------------
// Sliding-window attention with sinks.
// Grid (NB_, H_KV_). CTA loads K/V pair tile (256x64 each) into smem.
// Warp handles one query index qi at a time (uniform key range, no divergence).
// Lane = (g = lane>>2, chunk = lane&3): 8 q-heads x 4 chunks of 16 dims.
// Dot reduced across the 4 chunk lanes by shfl; online softmax per g.
// ---------------------------------------------------------------------------
__global__ void __launch_bounds__(256)
attn_kernel(const float* __restrict__ qkv, const float* __restrict__ sinks,
            float* __restrict__ out)
{
    extern __shared__ float sm[];
    float* Ks = sm;               // [256][64]
    float* Vs = sm + 256 * 64;    // [256][64]

    const int b  = blockIdx.x;
    const int kv = blockIdx.y;
    const int tid = threadIdx.x;

    // Load K/V pair tile: rows 0..127 = previous block, 128..255 = current.
    for (int idx = tid; idx < 256 * 16; idx += 256) {     // 4096 float4
        const int m  = idx >> 4;
        const int c4 = (idx & 15) << 2;
        float4 kk = make_float4(0.f, 0.f, 0.f, 0.f);
        float4 vv = kk;
        if (m >= 128 || b > 0) {
            const int tok = (m < 128) ? ((b - 1) * W_ + m) : (b * W_ + m - 128);
            const float* kp = qkv + (size_t)tok * QKV_OUT + 4096 + kv * 64 + c4;
            kk = *reinterpret_cast<const float4*>(kp);
            vv = *reinterpret_cast<const float4*>(kp + 512);   // v offset
        }
        *reinterpret_cast<float4*>(Ks + m * 64 + c4) = kk;
        *reinterpret_cast<float4*>(Vs + m * 64 + c4) = vv;
    }
    __syncthreads();

    const int warp  = tid >> 5;
    const int lane  = tid & 31;
    const int g     = lane >> 2;
    const int chunk = lane & 3;
    const int qh    = kv * G_ + g;
    const float sink = sinks[qh];

    for (int qi = warp; qi < W_; qi += 8) {
        const int tok = b * W_ + qi;
        const float* qp = qkv + (size_t)tok * QKV_OUT + qh * 64 + chunk * 16;
        float q[16];
#pragma unroll
        for (int j = 0; j < 4; j++) {
            float4 t4 = *reinterpret_cast<const float4*>(qp + j * 4);
            q[4 * j] = t4.x; q[4 * j + 1] = t4.y;
            q[4 * j + 2] = t4.z; q[4 * j + 3] = t4.w;
        }
        float mrun = sink;
        float denom = 1.f;          // exp(sink - mrun)
        float ctx[16];
#pragma unroll
        for (int i = 0; i < 16; i++) ctx[i] = 0.f;

        const int mstart = (b == 0) ? 128 : (qi + 1);
        const int mend   = qi + W_;      // inclusive

        for (int m = mstart; m <= mend; m++) {
            const float* kr = Ks + m * 64 + chunk * 16;
            float part = 0.f;
#pragma unroll
            for (int j = 0; j < 4; j++) {
                float4 k4 = *reinterpret_cast<const float4*>(kr + j * 4);
                part += q[4 * j] * k4.x + q[4 * j + 1] * k4.y +
                        q[4 * j + 2] * k4.z + q[4 * j + 3] * k4.w;
            }
            part += __shfl_xor_sync(0xffffffffu, part, 1);
            part += __shfl_xor_sync(0xffffffffu, part, 2);
            const float sc = part * 0.125f;

            float w;
            if (sc > mrun) {
                const float f = __expf(mrun - sc);
                denom = denom * f + 1.f;
#pragma unroll
                for (int i = 0; i < 16; i++) ctx[i] *= f;
                mrun = sc;
                w = 1.f;
            } else {
                w = __expf(sc - mrun);
                denom += w;
            }
            const float* vr = Vs + m * 64 + chunk * 16;
#pragma unroll
            for (int j = 0; j < 4; j++) {
                float4 v4 = *reinterpret_cast<const float4*>(vr + j * 4);
                ctx[4 * j]     += w * v4.x;
                ctx[4 * j + 1] += w * v4.y;
                ctx[4 * j + 2] += w * v4.z;
                ctx[4 * j + 3] += w * v4.w;
            }
        }
        const float inv = 1.f / denom;
        float* op = out + (size_t)tok * ATTN_W + qh * 64 + chunk * 16;
#pragma unroll
        for (int j = 0; j < 4; j++) {
            float4 o4 = make_float4(ctx[4 * j] * inv, ctx[4 * j + 1] * inv,
                                    ctx[4 * j + 2] * inv, ctx[4 * j + 3] * inv);
            *reinterpret_cast<float4*>(op + j * 4) = o4;
        }
    }
}

// ---------------------------------------------------------------------------
// kernel_launch
// inputs: 0 hidden_states [4096,2880] f32, 1 cos [4096,32], 2 sin [4096,32],
//         3 Wqkv [2880,5120], 4 b_qkv [5120], 5 Wo [4096,2880], 6 b_o [2880],
//         7 sinks [64], 8 positions [4096] i32 (unused)
// output: [4096, 2880] f32
// ---------------------------------------------------------------------------
extern "C" void kernel_launch(void* const* d_in, const int* in_sizes, int n_in,
                              void* d_out, int out_size)
{
    const float* hs    = (const float*)d_in[0];
    const float* cosb  = (const float*)d_in[1];
    const float* sinb  = (const float*)d_in[2];
    const float* Wqkv  = (const float*)d_in[3];
    const float* bqkv  = (const float*)d_in[4];
    const float* Wo    = (const float*)d_in[5];
    const float* bo    = (const float*)d_in[6];
    const float* sinks = (const float*)d_in[7];
    float* out = (float*)d_out;

    float* qkv;  cudaGetSymbolAddress((void**)&qkv,  g_qkv);
    float* attn; cudaGetSymbolAddress((void**)&attn, g_attn);

    cudaFuncSetAttribute(attn_kernel,
                         cudaFuncAttributeMaxDynamicSharedMemorySize, 131072);

    // 1) QKV projection
    dim3 g1(QKV_OUT / 128, S_LEN / 128);   // (40, 32)
    gemm_tf32<<<g1, 256>>>(hs, Wqkv, bqkv, qkv, S_LEN, QKV_OUT, HID_);

    // 2) RoPE on q and k
    const int total = S_LEN * 72 * HALF_;
    rope_kernel<<<(total + 255) / 256, 256>>>(qkv, cosb, sinb);

    // 3) Sliding-window attention with sinks
    dim3 g2(NB_, H_KV_);
    attn_kernel<<<g2, 256, 131072>>>(qkv, sinks, attn);

    // 4) Output projection
    dim3 g3((HID_ + 127) / 128, S_LEN / 128);   // (23, 32)
    gemm_tf32<<<g3, 256>>>(attn, Wo, bo, out, S_LEN, HID_, ATTN_W);
}

// round 3
// speedup vs baseline: 1.4489x; 1.4489x over previous
#include <cuda_runtime.h>
#include <cuda_fp16.h>
#include <cstdint>

#define S_LEN   4096
#define HID_    2880
#define H_Q_    64
#define H_KV_   8
#define G_      8
#define D_      64
#define HALF_   32
#define W_      128
#define NB_     32
#define QKV_OUT 5120
#define ATTN_W  4096

// ---------------------------------------------------------------------------
// Scratch
// ---------------------------------------------------------------------------
__device__ float  g_qkv    [(size_t)S_LEN * QKV_OUT];
__device__ __half g_hs_h   [(size_t)S_LEN * HID_];
__device__ __half g_wqkvT_h[(size_t)QKV_OUT * HID_];
__device__ __half g_woT_h  [(size_t)HID_ * ATTN_W];
__device__ __half g_attn_h [(size_t)S_LEN * ATTN_W];

// ---------------------------------------------------------------------------
// PTX helpers (plain sm_100 ISA only: cp.async + ldmatrix + mma.sync)
// ---------------------------------------------------------------------------
__device__ __forceinline__ uint32_t smem_u32(const void* p) {
    uint32_t a;
    asm("{ .reg .u64 t; cvta.to.shared.u64 t, %1; cvt.u32.u64 %0, t; }" : "=r"(a) : "l"(p));
    return a;
}
__device__ __forceinline__ void cpasync16(uint32_t dst, const void* src, uint32_t sz) {
    asm volatile("cp.async.cg.shared.global [%0], [%1], 16, %2;\n"
                 :: "r"(dst), "l"(src), "r"(sz) : "memory");
}
#define CP_COMMIT() asm volatile("cp.async.commit_group;" ::: "memory")
#define CP_WAIT2()  asm volatile("cp.async.wait_group 2;" ::: "memory")

#define LDSM_X4(d0, d1, d2, d3, a)                                             \
    asm volatile("ldmatrix.sync.aligned.m8n8.x4.shared.b16 {%0,%1,%2,%3}, [%4];"\
        : "=r"(d0), "=r"(d1), "=r"(d2), "=r"(d3) : "r"(a))

#define MMA_F16(d, a, b)                                                       \
    asm volatile("mma.sync.aligned.m16n8k16.row.col.f32.f16.f16.f32 "          \
        "{%0,%1,%2,%3}, {%4,%5,%6,%7}, {%8,%9}, {%0,%1,%2,%3};"                \
        : "+f"((d)[0]), "+f"((d)[1]), "+f"((d)[2]), "+f"((d)[3])               \
        : "r"((a)[0]), "r"((a)[1]), "r"((a)[2]), "r"((a)[3]),                  \
          "r"((b)[0]), "r"((b)[1]))

// ---------------------------------------------------------------------------
// fp16 GEMM:  C[M,Nn] = A[M,K] @ Bt[Nn,K]^T + bias   (A, Bt half; C fp32)
// CTA tile 128x128, K-step 32, 4-stage cp.async pipeline, 8 warps 4(M)x2(N).
// Smem layout per operand: rows of 64B (32 halfs), 16B-chunk swizzle
//   chunk' = chunk ^ ((row>>1)&3)   -> conflict-free ldmatrix + cp.async.
// ---------------------------------------------------------------------------
#define KSTEP       32
#define GSTAGES     4
#define STAGE_BYTES 16384   // A 8KB + B 8KB
#define GM_SMEM     (GSTAGES * STAGE_BYTES)

__global__ void __launch_bounds__(256, 2)
gemm_h(const __half* __restrict__ A, const __half* __restrict__ Bt,
       const float* __restrict__ bias, float* __restrict__ C,
       int Nn, int K)
{
    extern __shared__ char smem[];
    const uint32_t sb = smem_u32(smem);
    const int tid  = threadIdx.x;
    const int wid  = tid >> 5;
    const int lane = tid & 31;
    const int m0   = blockIdx.y << 7;
    const int n0   = blockIdx.x << 7;
    const int wm   = (wid & 3) << 5;    // warp M offset: 0,32,64,96
    const int wn   = (wid >> 2) << 6;   // warp N offset: 0,64

    float acc[2][8][4];
#pragma unroll
    for (int a = 0; a < 2; a++)
#pragma unroll
        for (int b = 0; b < 8; b++)
#pragma unroll
            for (int c = 0; c < 4; c++) acc[a][b][c] = 0.f;

    const int nkt = K >> 5;

    auto load_stage = [&](int kt, int slot) {
        const uint32_t abase = sb + slot * STAGE_BYTES;
        const uint32_t bbase = abase + 8192;
        const int k0 = kt << 5;
#pragma unroll
        for (int j = 0; j < 2; j++) {            // A: 128 rows x 4 chunks
            const int f = tid + (j << 8);
            const int r = f >> 2, c = f & 3;
            const uint32_t off = (uint32_t)(r << 6) + ((c ^ ((r >> 1) & 3)) << 4);
            cpasync16(abase + off, A + (size_t)(m0 + r) * K + k0 + (c << 3), 16u);
        }
#pragma unroll
        for (int j = 0; j < 2; j++) {            // B: 128 n-rows x 4 chunks
            const int f = tid + (j << 8);
            const int r = f >> 2, c = f & 3;
            const uint32_t off = (uint32_t)(r << 6) + ((c ^ ((r >> 1) & 3)) << 4);
            const int nrow = n0 + r;
            const int srow = (nrow < Nn) ? nrow : 0;
            cpasync16(bbase + off, Bt + (size_t)srow * K + k0 + (c << 3),
                      (nrow < Nn) ? 16u : 0u);
        }
    };

    // prologue: 3 stages in flight
    for (int s = 0; s < GSTAGES - 1; s++) {
        if (s < nkt) load_stage(s, s);
        CP_COMMIT();
    }

    // ldmatrix lane-fixed address components
    const int a_rl = lane & 15;            // row within m16
    const int a_cl = lane >> 4;            // chunk offset 0/1
    const int b_nl = ((lane >> 4) << 3) + (lane & 7);
    const int b_cl = (lane >> 3) & 1;

    for (int t = 0; t < nkt; t++) {
        CP_WAIT2();
        __syncthreads();
        const uint32_t abase = sb + (t & 3) * STAGE_BYTES;
        const uint32_t bbase = abase + 8192;

#pragma unroll
        for (int kh = 0; kh < 2; kh++) {         // two k16 halves of K=32
            const int kc = kh << 1;
            uint32_t af[2][4];
#pragma unroll
            for (int mt = 0; mt < 2; mt++) {
                const int r = wm + (mt << 4) + a_rl;
                const int c = kc + a_cl;
                const uint32_t addr =
                    abase + (uint32_t)(r << 6) + ((c ^ ((r >> 1) & 3)) << 4);
                LDSM_X4(af[mt][0], af[mt][1], af[mt][2], af[mt][3], addr);
            }
            uint32_t bf[8][2];
#pragma unroll
            for (int nq = 0; nq < 4; nq++) {     // 16 n per x4 ldmatrix
                const int r = wn + (nq << 4) + b_nl;
                const int c = kc + b_cl;
                const uint32_t addr =
                    bbase + (uint32_t)(r << 6) + ((c ^ ((r >> 1) & 3)) << 4);
                uint32_t t0, t1, t2, t3;
                LDSM_X4(t0, t1, t2, t3, addr);
                bf[nq * 2][0] = t0;     bf[nq * 2][1] = t1;
                bf[nq * 2 + 1][0] = t2; bf[nq * 2 + 1][1] = t3;
            }
#pragma unroll
            for (int mt = 0; mt < 2; mt++)
#pragma unroll
                for (int nt = 0; nt < 8; nt++)
                    MMA_F16(acc[mt][nt], af[mt], bf[nt]);
        }

        const int tn = t + 3;
        if (tn < nkt) load_stage(tn, tn & 3);
        CP_COMMIT();
    }

    // epilogue
    const int r_l = lane >> 2;
    const int c_l = (lane & 3) << 1;
#pragma unroll
    for (int mt = 0; mt < 2; mt++) {
        const int row = m0 + wm + (mt << 4) + r_l;
#pragma unroll
        for (int nt = 0; nt < 8; nt++) {
            const int col = n0 + wn + (nt << 3) + c_l;
            if (col < Nn) {
                const float2 bz = *reinterpret_cast<const float2*>(bias + col);
                float2 o0, o1;
                o0.x = acc[mt][nt][0] + bz.x;  o0.y = acc[mt][nt][1] + bz.y;
                o1.x = acc[mt][nt][2] + bz.x;  o1.y = acc[mt][nt][3] + bz.y;
                *reinterpret_cast<float2*>(C + (size_t)row * Nn + col)       = o0;
                *reinterpret_cast<float2*>(C + (size_t)(row + 8) * Nn + col) = o1;
            }
        }
    }
}

// ---------------------------------------------------------------------------
// Prep kernels
// ---------------------------------------------------------------------------
__global__ void f2h_kernel(const float* __restrict__ src, __half* __restrict__ dst,
                           int n4)
{
    const int i = blockIdx.x * blockDim.x + threadIdx.x;
    if (i >= n4) return;
    const float4 v = reinterpret_cast<const float4*>(src)[i];
    __half2* d = reinterpret_cast<__half2*>(dst) + 2 * i;
    d[0] = __floats2half2_rn(v.x, v.y);
    d[1] = __floats2half2_rn(v.z, v.w);
}

__global__ void transpose_h(const float* __restrict__ src, __half* __restrict__ dst,
                            int R, int Cc)   // src [R,Cc] -> dst [Cc,R] (half)
{
    __shared__ float t[32][33];
    const int bx = blockIdx.x << 5;
    const int by = blockIdx.y << 5;
    const int tx = threadIdx.x, ty = threadIdx.y;
#pragma unroll
    for (int i = 0; i < 4; i++)
        t[ty + (i << 3)][tx] = src[(size_t)(by + ty + (i << 3)) * Cc + bx + tx];
    __syncthreads();
#pragma unroll
    for (int i = 0; i < 4; i++)
        dst[(size_t)(bx + ty + (i << 3)) * R + by + tx] =
            __float2half(t[tx][ty + (i << 3)]);
}

// ---------------------------------------------------------------------------
// RoPE (neox), in-place on q/k heads of g_qkv
// ---------------------------------------------------------------------------
__global__ void rope_kernel(float* __restrict__ qkv,
                            const float* __restrict__ cosb,
                            const float* __restrict__ sinb)
{
    const int idx = blockIdx.x * blockDim.x + threadIdx.x;
    const int total = S_LEN * 72 * HALF_;
    if (idx >= total) return;
    const int d = idx & 31;
    const int h = (idx >> 5) % 72;
    const int s = idx / (72 * 32);
    const size_t base = (size_t)s * QKV_OUT + h * 64;
    const float x1 = qkv[base + d];
    const float x2 = qkv[base + d + 32];
    const float c  = cosb[s * 32 + d];
    const float sn = sinb[s * 32 + d];
    qkv[base + d]      = x1 * c - x2 * sn;
    qkv[base + d + 32] = x2 * c + x1 * sn;
}

// ---------------------------------------------------------------------------
// Sliding-window attention with sinks: two-pass branch-free softmax.
// Writes fp16 (feeds the fp16 O-proj GEMM directly).
// ---------------------------------------------------------------------------
__global__ void __launch_bounds__(256)
attn_kernel(const float* __restrict__ qkv, const float* __restrict__ sinks,
            __half* __restrict__ out)
{
    extern __shared__ float sm[];
    float* Ks = sm;
    float* Vs = sm + 256 * 64;

    const int b   = blockIdx.x;
    const int kv  = blockIdx.y;
    const int tid = threadIdx.x;

    for (int idx = tid; idx < 256 * 16; idx += 256) {
        const int m  = idx >> 4;
        const int c4 = (idx & 15) << 2;
        float4 kk = make_float4(0.f, 0.f, 0.f, 0.f);
        float4 vv = kk;
        if (m >= 128 || b > 0) {
            const int tok = (m < 128) ? ((b - 1) * W_ + m) : (b * W_ + m - 128);
            const float* kp = qkv + (size_t)tok * QKV_OUT + 4096 + kv * 64 + c4;
            kk = *reinterpret_cast<const float4*>(kp);
            vv = *reinterpret_cast<const float4*>(kp + 512);
        }
        *reinterpret_cast<float4*>(Ks + m * 64 + c4) = kk;
        *reinterpret_cast<float4*>(Vs + m * 64 + c4) = vv;
    }
    __syncthreads();

    const int warp  = tid >> 5;
    const int lane  = tid & 31;
    const int chunk = lane & 3;
    const int qh    = kv * G_ + (lane >> 2);
    const float sink = sinks[qh];

    for (int qi = warp; qi < W_; qi += 8) {
        const int tok = b * W_ + qi;
        const float* qp = qkv + (size_t)tok * QKV_OUT + qh * 64 + chunk * 16;
        float q[16];
#pragma unroll
        for (int j = 0; j < 4; j++) {
            const float4 t4 = *reinterpret_cast<const float4*>(qp + j * 4);
            q[4 * j]     = t4.x * 0.125f;
            q[4 * j + 1] = t4.y * 0.125f;
            q[4 * j + 2] = t4.z * 0.125f;
            q[4 * j + 3] = t4.w * 0.125f;
        }

        const int mstart = (b == 0) ? 128 : (qi + 1);
        const int mend   = qi + W_;

        // pass 1: global max
        float mrun = sink;
#pragma unroll 4
        for (int m = mstart; m <= mend; m++) {
            const float* kr = Ks + m * 64 + chunk * 16;
            float part = 0.f;
#pragma unroll
            for (int j = 0; j < 4; j++) {
                const float4 k4 = *reinterpret_cast<const float4*>(kr + j * 4);
                part += q[4 * j] * k4.x + q[4 * j + 1] * k4.y +
                        q[4 * j + 2] * k4.z + q[4 * j + 3] * k4.w;
            }
            part += __shfl_xor_sync(0xffffffffu, part, 1);
            part += __shfl_xor_sync(0xffffffffu, part, 2);
            mrun = fmaxf(mrun, part);
        }

        // pass 2: exp + accumulate
        float denom = __expf(sink - mrun);
        float ctx[16];
#pragma unroll
        for (int i = 0; i < 16; i++) ctx[i] = 0.f;

#pragma unroll 2
        for (int m = mstart; m <= mend; m++) {
            const float* kr = Ks + m * 64 + chunk * 16;
            float part = 0.f;
#pragma unroll
            for (int j = 0; j < 4; j++) {
                const float4 k4 = *reinterpret_cast<const float4*>(kr + j * 4);
                part += q[4 * j] * k4.x + q[4 * j + 1] * k4.y +
                        q[4 * j + 2] * k4.z + q[4 * j + 3] * k4.w;
            }
            part += __shfl_xor_sync(0xffffffffu, part, 1);
            part += __shfl_xor_sync(0xffffffffu, part, 2);
            const float w = __expf(part - mrun);
            denom += w;
            const float* vr = Vs + m * 64 + chunk * 16;
#pragma unroll
            for (int j = 0; j < 4; j++) {
                const float4 v4 = *reinterpret_cast<const float4*>(vr + j * 4);
                ctx[4 * j]     += w * v4.x;
                ctx[4 * j + 1] += w * v4.y;
                ctx[4 * j + 2] += w * v4.z;
                ctx[4 * j + 3] += w * v4.w;
            }
        }
        const float inv = 1.f / denom;
        __half2* op = reinterpret_cast<__half2*>(
            out + (size_t)tok * ATTN_W + qh * 64 + chunk * 16);
#pragma unroll
        for (int j = 0; j < 8; j++)
            op[j] = __floats2half2_rn(ctx[2 * j] * inv, ctx[2 * j + 1] * inv);
    }
}

// ---------------------------------------------------------------------------
// kernel_launch
// ---------------------------------------------------------------------------
extern "C" void kernel_launch(void* const* d_in, const int* in_sizes, int n_in,
                              void* d_out, int out_size)
{
    const float* hs    = (const float*)d_in[0];
    const float* cosb  = (const float*)d_in[1];
    const float* sinb  = (const float*)d_in[2];
    const float* Wqkv  = (const float*)d_in[3];
    const float* bqkv  = (const float*)d_in[4];
    const float* Wo    = (const float*)d_in[5];
    const float* bo    = (const float*)d_in[6];
    const float* sinks = (const float*)d_in[7];
    float* out = (float*)d_out;

    float*  qkv;   cudaGetSymbolAddress((void**)&qkv,   g_qkv);
    __half* hsh;   cudaGetSymbolAddress((void**)&hsh,   g_hs_h);
    __half* wqkvT; cudaGetSymbolAddress((void**)&wqkvT, g_wqkvT_h);
    __half* woT;   cudaGetSymbolAddress((void**)&woT,   g_woT_h);
    __half* attnh; cudaGetSymbolAddress((void**)&attnh, g_attn_h);

    cudaFuncSetAttribute(gemm_h,
                         cudaFuncAttributeMaxDynamicSharedMemorySize, GM_SMEM);
    cudaFuncSetAttribute(attn_kernel,
                         cudaFuncAttributeMaxDynamicSharedMemorySize, 131072);

    // 0) operand prep: fp32 -> fp16 (A), transpose+convert (B)
    {
        const int n4 = S_LEN * HID_ / 4;
        f2h_kernel<<<(n4 + 255) / 256, 256>>>(hs, hsh, n4);
        dim3 blk(32, 8);
        transpose_h<<<dim3(QKV_OUT / 32, HID_ / 32), blk>>>(Wqkv, wqkvT, HID_, QKV_OUT);
        transpose_h<<<dim3(HID_ / 32, ATTN_W / 32), blk>>>(Wo, woT, ATTN_W, HID_);
    }

    // 1) QKV projection: [4096,2880] @ [2880,5120] -> fp32
    gemm_h<<<dim3(QKV_OUT / 128, S_LEN / 128), 256, GM_SMEM>>>(
        hsh, wqkvT, bqkv, qkv, QKV_OUT, HID_);

    // 2) RoPE
    const int total = S_LEN * 72 * HALF_;
    rope_kernel<<<(total + 255) / 256, 256>>>(qkv, cosb, sinb);

    // 3) attention (writes fp16)
    attn_kernel<<<dim3(NB_, H_KV_), 256, 131072>>>(qkv, sinks, attnh);

    // 4) output projection: [4096,4096] @ [4096,2880] -> fp32
    gemm_h<<<dim3((HID_ + 127) / 128, S_LEN / 128), 256, GM_SMEM>>>(
        attnh, woT, bo, out, HID_, ATTN_W);
}

// round 4
// speedup vs baseline: 4.5189x; 3.1188x over previous
#include <cuda_runtime.h>
#include <cuda_fp16.h>
#include <cstdint>

#define S_LEN   4096
#define HID_    2880
#define H_KV_   8
#define G_      8
#define W_      128
#define NB_     32
#define QKV_OUT 5120
#define ATTN_W  4096
#define HALF_   32

// ---------------------------------------------------------------------------
// Scratch
// ---------------------------------------------------------------------------
__device__ float  g_qkv    [(size_t)S_LEN * QKV_OUT];
__device__ __half g_hs_h   [(size_t)S_LEN * HID_];
__device__ __half g_wqkvT_h[(size_t)QKV_OUT * HID_];
__device__ __half g_woT_h  [(size_t)HID_ * ATTN_W];
__device__ __half g_attn_h [(size_t)S_LEN * ATTN_W];

// ---------------------------------------------------------------------------
// PTX helpers (plain sm_100 ISA)
// ---------------------------------------------------------------------------
__device__ __forceinline__ uint32_t smem_u32(const void* p) {
    uint32_t a;
    asm("{ .reg .u64 t; cvta.to.shared.u64 t, %1; cvt.u32.u64 %0, t; }" : "=r"(a) : "l"(p));
    return a;
}
__device__ __forceinline__ void cpasync16(uint32_t dst, const void* src, uint32_t sz) {
    asm volatile("cp.async.cg.shared.global [%0], [%1], 16, %2;\n"
                 :: "r"(dst), "l"(src), "r"(sz) : "memory");
}
#define CP_COMMIT() asm volatile("cp.async.commit_group;" ::: "memory")
#define CP_WAIT2()  asm volatile("cp.async.wait_group 2;" ::: "memory")

#define LDSM_X4(d0, d1, d2, d3, a)                                             \
    asm volatile("ldmatrix.sync.aligned.m8n8.x4.shared.b16 {%0,%1,%2,%3}, [%4];"\
        : "=r"(d0), "=r"(d1), "=r"(d2), "=r"(d3) : "r"(a))

#define LDSM_X4_T(d0, d1, d2, d3, a)                                           \
    asm volatile("ldmatrix.sync.aligned.m8n8.x4.trans.shared.b16 {%0,%1,%2,%3}, [%4];"\
        : "=r"(d0), "=r"(d1), "=r"(d2), "=r"(d3) : "r"(a))

#define MMA_F16(d, a, b)                                                       \
    asm volatile("mma.sync.aligned.m16n8k16.row.col.f32.f16.f16.f32 "          \
        "{%0,%1,%2,%3}, {%4,%5,%6,%7}, {%8,%9}, {%0,%1,%2,%3};"                \
        : "+f"((d)[0]), "+f"((d)[1]), "+f"((d)[2]), "+f"((d)[3])               \
        : "r"((a)[0]), "r"((a)[1]), "r"((a)[2]), "r"((a)[3]),                  \
          "r"((b)[0]), "r"((b)[1]))

__device__ __forceinline__ uint32_t pack_h2(float x, float y) {
    __half2 h = __floats2half2_rn(x, y);
    return *reinterpret_cast<uint32_t*>(&h);
}

// ---------------------------------------------------------------------------
// fp16 GEMM (unchanged from round 3): C[M,Nn] = A @ Bt^T + bias
// ---------------------------------------------------------------------------
#define GSTAGES     4
#define STAGE_BYTES 16384
#define GM_SMEM     (GSTAGES * STAGE_BYTES)

__global__ void __launch_bounds__(256, 2)
gemm_h(const __half* __restrict__ A, const __half* __restrict__ Bt,
       const float* __restrict__ bias, float* __restrict__ C,
       int Nn, int K)
{
    extern __shared__ char smem[];
    const uint32_t sb = smem_u32(smem);
    const int tid  = threadIdx.x;
    const int wid  = tid >> 5;
    const int lane = tid & 31;
    const int m0   = blockIdx.y << 7;
    const int n0   = blockIdx.x << 7;
    const int wm   = (wid & 3) << 5;
    const int wn   = (wid >> 2) << 6;

    float acc[2][8][4];
#pragma unroll
    for (int a = 0; a < 2; a++)
#pragma unroll
        for (int b = 0; b < 8; b++)
#pragma unroll
            for (int c = 0; c < 4; c++) acc[a][b][c] = 0.f;

    const int nkt = K >> 5;

    auto load_stage = [&](int kt, int slot) {
        const uint32_t abase = sb + slot * STAGE_BYTES;
        const uint32_t bbase = abase + 8192;
        const int k0 = kt << 5;
#pragma unroll
        for (int j = 0; j < 2; j++) {
            const int f = tid + (j << 8);
            const int r = f >> 2, c = f & 3;
            const uint32_t off = (uint32_t)(r << 6) + ((c ^ ((r >> 1) & 3)) << 4);
            cpasync16(abase + off, A + (size_t)(m0 + r) * K + k0 + (c << 3), 16u);
        }
#pragma unroll
        for (int j = 0; j < 2; j++) {
            const int f = tid + (j << 8);
            const int r = f >> 2, c = f & 3;
            const uint32_t off = (uint32_t)(r << 6) + ((c ^ ((r >> 1) & 3)) << 4);
            const int nrow = n0 + r;
            const int srow = (nrow < Nn) ? nrow : 0;
            cpasync16(bbase + off, Bt + (size_t)srow * K + k0 + (c << 3),
                      (nrow < Nn) ? 16u : 0u);
        }
    };

    for (int s = 0; s < GSTAGES - 1; s++) {
        if (s < nkt) load_stage(s, s);
        CP_COMMIT();
    }

    const int a_rl = lane & 15;
    const int a_cl = lane >> 4;
    const int b_nl = ((lane >> 4) << 3) + (lane & 7);
    const int b_cl = (lane >> 3) & 1;

    for (int t = 0; t < nkt; t++) {
        CP_WAIT2();
        __syncthreads();
        const uint32_t abase = sb + (t & 3) * STAGE_BYTES;
        const uint32_t bbase = abase + 8192;

#pragma unroll
        for (int kh = 0; kh < 2; kh++) {
            const int kc = kh << 1;
            uint32_t af[2][4];
#pragma unroll
            for (int mt = 0; mt < 2; mt++) {
                const int r = wm + (mt << 4) + a_rl;
                const int c = kc + a_cl;
                const uint32_t addr =
                    abase + (uint32_t)(r << 6) + ((c ^ ((r >> 1) & 3)) << 4);
                LDSM_X4(af[mt][0], af[mt][1], af[mt][2], af[mt][3], addr);
            }
            uint32_t bf[8][2];
#pragma unroll
            for (int nq = 0; nq < 4; nq++) {
                const int r = wn + (nq << 4) + b_nl;
                const int c = kc + b_cl;
                const uint32_t addr =
                    bbase + (uint32_t)(r << 6) + ((c ^ ((r >> 1) & 3)) << 4);
                uint32_t t0, t1, t2, t3;
                LDSM_X4(t0, t1, t2, t3, addr);
                bf[nq * 2][0] = t0;     bf[nq * 2][1] = t1;
                bf[nq * 2 + 1][0] = t2; bf[nq * 2 + 1][1] = t3;
            }
#pragma unroll
            for (int mt = 0; mt < 2; mt++)
#pragma unroll
                for (int nt = 0; nt < 8; nt++)
                    MMA_F16(acc[mt][nt], af[mt], bf[nt]);
        }

        const int tn = t + 3;
        if (tn < nkt) load_stage(tn, tn & 3);
        CP_COMMIT();
    }

    const int r_l = lane >> 2;
    const int c_l = (lane & 3) << 1;
#pragma unroll
    for (int mt = 0; mt < 2; mt++) {
        const int row = m0 + wm + (mt << 4) + r_l;
#pragma unroll
        for (int nt = 0; nt < 8; nt++) {
            const int col = n0 + wn + (nt << 3) + c_l;
            if (col < Nn) {
                const float2 bz = *reinterpret_cast<const float2*>(bias + col);
                float2 o0, o1;
                o0.x = acc[mt][nt][0] + bz.x;  o0.y = acc[mt][nt][1] + bz.y;
                o1.x = acc[mt][nt][2] + bz.x;  o1.y = acc[mt][nt][3] + bz.y;
                *reinterpret_cast<float2*>(C + (size_t)row * Nn + col)       = o0;
                *reinterpret_cast<float2*>(C + (size_t)(row + 8) * Nn + col) = o1;
            }
        }
    }
}

// ---------------------------------------------------------------------------
// Prep kernels
// ---------------------------------------------------------------------------
__global__ void f2h_kernel(const float* __restrict__ src, __half* __restrict__ dst,
                           int n4)
{
    const int i = blockIdx.x * blockDim.x + threadIdx.x;
    if (i >= n4) return;
    const float4 v = reinterpret_cast<const float4*>(src)[i];
    __half2* d = reinterpret_cast<__half2*>(dst) + 2 * i;
    d[0] = __floats2half2_rn(v.x, v.y);
    d[1] = __floats2half2_rn(v.z, v.w);
}

__global__ void transpose_h(const float* __restrict__ src, __half* __restrict__ dst,
                            int R, int Cc)
{
    __shared__ float t[32][33];
    const int bx = blockIdx.x << 5;
    const int by = blockIdx.y << 5;
    const int tx = threadIdx.x, ty = threadIdx.y;
#pragma unroll
    for (int i = 0; i < 4; i++)
        t[ty + (i << 3)][tx] = src[(size_t)(by + ty + (i << 3)) * Cc + bx + tx];
    __syncthreads();
#pragma unroll
    for (int i = 0; i < 4; i++)
        dst[(size_t)(bx + ty + (i << 3)) * R + by + tx] =
            __float2half(t[tx][ty + (i << 3)]);
}

// ---------------------------------------------------------------------------
// RoPE (neox), in-place on q/k heads of g_qkv
// ---------------------------------------------------------------------------
__global__ void rope_kernel(float* __restrict__ qkv,
                            const float* __restrict__ cosb,
                            const float* __restrict__ sinb)
{
    const int idx = blockIdx.x * blockDim.x + threadIdx.x;
    const int total = S_LEN * 72 * HALF_;
    if (idx >= total) return;
    const int d = idx & 31;
    const int h = (idx >> 5) % 72;
    const int s = idx / (72 * 32);
    const size_t base = (size_t)s * QKV_OUT + h * 64;
    const float x1 = qkv[base + d];
    const float x2 = qkv[base + d + 32];
    const float c  = cosb[s * 32 + d];
    const float sn = sinb[s * 32 + d];
    qkv[base + d]      = x1 * c - x2 * sn;
    qkv[base + d + 32] = x2 * c + x1 * sn;
}

// ---------------------------------------------------------------------------
// Tensor-core sliding-window flash attention with sinks.
// CTA = (block b, kv head). K/V pair tiles (256x64 fp16) resident in smem;
// loop g = 0..7 q-heads: S = Q K^T (mma), in-register mask+softmax with
// 2-chunk online rescale, P V accumulated fp32. Writes fp16 for O-proj.
// Smem rows 128B, 16B-chunk swizzle: chunk' = chunk ^ (row & 7).
// ---------------------------------------------------------------------------
#define AT_SMEM 81920   // K 32KB | V 32KB | Q 16KB

__device__ __forceinline__ void st8h(char* p, float4 a, float4 b) {
    uint4 u;
    u.x = pack_h2(a.x, a.y);
    u.y = pack_h2(a.z, a.w);
    u.z = pack_h2(b.x, b.y);
    u.w = pack_h2(b.z, b.w);
    *reinterpret_cast<uint4*>(p) = u;
}

__global__ void __launch_bounds__(256, 1)
attn_tc(const float* __restrict__ qkv, const float* __restrict__ sinks,
        __half* __restrict__ out)
{
    extern __shared__ __align__(16) char asmem[];
    char* Kc = asmem;
    char* Vc = asmem + 32768;
    char* Qc = asmem + 65536;
    const uint32_t kb = smem_u32(Kc);
    const uint32_t vb = smem_u32(Vc);
    const uint32_t qb = smem_u32(Qc);

    const int b    = blockIdx.x;
    const int kv   = blockIdx.y;
    const int tid  = threadIdx.x;
    const int wid  = tid >> 5;
    const int lane = tid & 31;

    // ---- load K/V pair tiles (fp32 -> fp16, swizzled) ----
    for (int i = tid; i < 2048; i += 256) {
        const int tk = i >> 3, c = i & 7;
        float4 k0 = make_float4(0.f, 0.f, 0.f, 0.f), k1 = k0, v0 = k0, v1 = k0;
        if (tk >= 128 || b > 0) {
            const int token = (tk < 128) ? ((b - 1) * W_ + tk) : (b * W_ + tk - 128);
            const float* kp = qkv + (size_t)token * QKV_OUT + 4096 + kv * 64 + c * 8;
            k0 = *reinterpret_cast<const float4*>(kp);
            k1 = *reinterpret_cast<const float4*>(kp + 4);
            v0 = *reinterpret_cast<const float4*>(kp + 512);
            v1 = *reinterpret_cast<const float4*>(kp + 516);
        }
        const uint32_t off = (uint32_t)(tk << 7) + ((c ^ (tk & 7)) << 4);
        st8h(Kc + off, k0, k1);
        st8h(Vc + off, v0, v1);
    }

    const int q0    = wid << 4;            // warp's 16 query rows
    const int r_lo  = lane >> 2;
    const int cpair = (lane & 3) << 1;

    for (int g = 0; g < G_; g++) {
        __syncthreads();                   // prior-g Q reads done (or K/V load, g=0)
        // ---- stage Q_g (scaled by 1/8) ----
        for (int i = tid; i < 1024; i += 256) {
            const int r = i >> 3, c = i & 7;
            const float* qp = qkv + (size_t)(b * W_ + r) * QKV_OUT
                              + (kv * G_ + g) * 64 + c * 8;
            float4 a = *reinterpret_cast<const float4*>(qp);
            float4 d = *reinterpret_cast<const float4*>(qp + 4);
            a.x *= 0.125f; a.y *= 0.125f; a.z *= 0.125f; a.w *= 0.125f;
            d.x *= 0.125f; d.y *= 0.125f; d.z *= 0.125f; d.w *= 0.125f;
            st8h(Qc + (r << 7) + ((c ^ (r & 7)) << 4), a, d);
        }
        __syncthreads();

        // ---- Q fragments (K=64 -> 4 k-steps), reused for both key chunks ----
        uint32_t aq[4][4];
#pragma unroll
        for (int kt = 0; kt < 4; kt++) {
            const int row = q0 + (lane & 15);
            const int ch  = (kt << 1) + (lane >> 4);
            const uint32_t addr = qb + (uint32_t)(row << 7) + ((ch ^ (row & 7)) << 4);
            LDSM_X4(aq[kt][0], aq[kt][1], aq[kt][2], aq[kt][3], addr);
        }

        const float sink = sinks[kv * G_ + g];
        float m0 = sink, m1 = sink;        // running max (rows lo / hi)
        float dn0 = 1.f, dn1 = 1.f;        // running denom (incl. sink term)
        float o[8][4];
#pragma unroll
        for (int j = 0; j < 8; j++)
#pragma unroll
            for (int c = 0; c < 4; c++) o[j][c] = 0.f;

#pragma unroll
        for (int ch2 = 0; ch2 < 2; ch2++) {
            if (b == 0 && ch2 == 0) continue;   // first block: prev half fully masked

            // ---- S = Q K^T over 128 keys ----
            float s[16][4];
#pragma unroll
            for (int nt = 0; nt < 16; nt++)
#pragma unroll
                for (int c = 0; c < 4; c++) s[nt][c] = 0.f;

#pragma unroll
            for (int nt2 = 0; nt2 < 8; nt2++) {
#pragma unroll
                for (int kt = 0; kt < 4; kt++) {
                    const int row = (ch2 << 7) + (nt2 << 4)
                                    + ((lane >> 4) << 3) + (lane & 7);
                    const int cc  = (kt << 1) + ((lane >> 3) & 1);
                    const uint32_t addr =
                        kb + (uint32_t)(row << 7) + ((cc ^ (row & 7)) << 4);
                    uint32_t t0, t1, t2, t3;
                    LDSM_X4(t0, t1, t2, t3, addr);
                    uint32_t bf0[2] = {t0, t1}, bf1[2] = {t2, t3};
                    MMA_F16(s[nt2 * 2],     aq[kt], bf0);
                    MMA_F16(s[nt2 * 2 + 1], aq[kt], bf1);
                }
            }

            // ---- mask: valid iff 1 <= ki - qi <= 128 ----
            const int qi_lo = q0 + r_lo;
            const int qi_hi = qi_lo + 8;
#pragma unroll
            for (int nt = 0; nt < 16; nt++) {
                const int ki = (ch2 << 7) + (nt << 3) + cpair;
                const int d0i = ki - qi_lo, d1i = ki + 1 - qi_lo;
                const int d2i = ki - qi_hi, d3i = ki + 1 - qi_hi;
                if (d0i < 1 || d0i > 128) s[nt][0] = -1e30f;
                if (d1i < 1 || d1i > 128) s[nt][1] = -1e30f;
                if (d2i < 1 || d2i > 128) s[nt][2] = -1e30f;
                if (d3i < 1 || d3i > 128) s[nt][3] = -1e30f;
            }

            // ---- online softmax (chunk) ----
            float mx0 = -1e30f, mx1 = -1e30f;
#pragma unroll
            for (int nt = 0; nt < 16; nt++) {
                mx0 = fmaxf(mx0, fmaxf(s[nt][0], s[nt][1]));
                mx1 = fmaxf(mx1, fmaxf(s[nt][2], s[nt][3]));
            }
            mx0 = fmaxf(mx0, __shfl_xor_sync(0xffffffffu, mx0, 1));
            mx0 = fmaxf(mx0, __shfl_xor_sync(0xffffffffu, mx0, 2));
            mx1 = fmaxf(mx1, __shfl_xor_sync(0xffffffffu, mx1, 1));
            mx1 = fmaxf(mx1, __shfl_xor_sync(0xffffffffu, mx1, 2));
            const float nm0 = fmaxf(m0, mx0), nm1 = fmaxf(m1, mx1);
            const float f0 = __expf(m0 - nm0), f1 = __expf(m1 - nm1);

            float sum0 = 0.f, sum1 = 0.f;
            uint32_t p[16][2];
#pragma unroll
            for (int nt = 0; nt < 16; nt++) {
                const float e0 = __expf(s[nt][0] - nm0);
                const float e1 = __expf(s[nt][1] - nm0);
                const float e2 = __expf(s[nt][2] - nm1);
                const float e3 = __expf(s[nt][3] - nm1);
                sum0 += e0 + e1;
                sum1 += e2 + e3;
                p[nt][0] = pack_h2(e0, e1);
                p[nt][1] = pack_h2(e2, e3);
            }
            sum0 += __shfl_xor_sync(0xffffffffu, sum0, 1);
            sum0 += __shfl_xor_sync(0xffffffffu, sum0, 2);
            sum1 += __shfl_xor_sync(0xffffffffu, sum1, 1);
            sum1 += __shfl_xor_sync(0xffffffffu, sum1, 2);
            dn0 = dn0 * f0 + sum0;
            dn1 = dn1 * f1 + sum1;
            m0 = nm0; m1 = nm1;
#pragma unroll
            for (int j = 0; j < 8; j++) {
                o[j][0] *= f0; o[j][1] *= f0;
                o[j][2] *= f1; o[j][3] *= f1;
            }

            // ---- O += P V (P fragments directly from acc layout) ----
#pragma unroll
            for (int kt2 = 0; kt2 < 8; kt2++) {
                uint32_t ap[4] = { p[2 * kt2][0],     p[2 * kt2][1],
                                   p[2 * kt2 + 1][0], p[2 * kt2 + 1][1] };
#pragma unroll
                for (int nq = 0; nq < 4; nq++) {
                    const int row = (ch2 << 7) + (kt2 << 4) + (lane & 15);
                    const int cc  = (nq << 1) + (lane >> 4);
                    const uint32_t addr =
                        vb + (uint32_t)(row << 7) + ((cc ^ (row & 7)) << 4);
                    uint32_t t0, t1, t2, t3;
                    LDSM_X4_T(t0, t1, t2, t3, addr);
                    uint32_t b0[2] = {t0, t1}, b1[2] = {t2, t3};
                    MMA_F16(o[2 * nq],     ap, b0);
                    MMA_F16(o[2 * nq + 1], ap, b1);
                }
            }
        }

        // ---- epilogue: normalize, write fp16 ----
        const float i0 = 1.f / dn0, i1 = 1.f / dn1;
        const int tok_lo = b * W_ + q0 + r_lo;
        const int tok_hi = tok_lo + 8;
        const int colb   = (kv * G_ + g) * 64 + cpair;
#pragma unroll
        for (int nt = 0; nt < 8; nt++) {
            const uint32_t w0 = pack_h2(o[nt][0] * i0, o[nt][1] * i0);
            const uint32_t w1 = pack_h2(o[nt][2] * i1, o[nt][3] * i1);
            *reinterpret_cast<uint32_t*>(out + (size_t)tok_lo * ATTN_W + colb + nt * 8) = w0;
            *reinterpret_cast<uint32_t*>(out + (size_t)tok_hi * ATTN_W + colb + nt * 8) = w1;
        }
    }
}

// ---------------------------------------------------------------------------
// kernel_launch
// ---------------------------------------------------------------------------
extern "C" void kernel_launch(void* const* d_in, const int* in_sizes, int n_in,
                              void* d_out, int out_size)
{
    const float* hs    = (const float*)d_in[0];
    const float* cosb  = (const float*)d_in[1];
    const float* sinb  = (const float*)d_in[2];
    const float* Wqkv  = (const float*)d_in[3];
    const float* bqkv  = (const float*)d_in[4];
    const float* Wo    = (const float*)d_in[5];
    const float* bo    = (const float*)d_in[6];
    const float* sinks = (const float*)d_in[7];
    float* out = (float*)d_out;

    float*  qkv;   cudaGetSymbolAddress((void**)&qkv,   g_qkv);
    __half* hsh;   cudaGetSymbolAddress((void**)&hsh,   g_hs_h);
    __half* wqkvT; cudaGetSymbolAddress((void**)&wqkvT, g_wqkvT_h);
    __half* woT;   cudaGetSymbolAddress((void**)&woT,   g_woT_h);
    __half* attnh; cudaGetSymbolAddress((void**)&attnh, g_attn_h);

    cudaFuncSetAttribute(gemm_h,
                         cudaFuncAttributeMaxDynamicSharedMemorySize, GM_SMEM);
    cudaFuncSetAttribute(attn_tc,
                         cudaFuncAttributeMaxDynamicSharedMemorySize, AT_SMEM);

    // 0) operand prep
    {
        const int n4 = S_LEN * HID_ / 4;
        f2h_kernel<<<(n4 + 255) / 256, 256>>>(hs, hsh, n4);
        dim3 blk(32, 8);
        transpose_h<<<dim3(QKV_OUT / 32, HID_ / 32), blk>>>(Wqkv, wqkvT, HID_, QKV_OUT);
        transpose_h<<<dim3(HID_ / 32, ATTN_W / 32), blk>>>(Wo, woT, ATTN_W, HID_);
    }

    // 1) QKV projection
    gemm_h<<<dim3(QKV_OUT / 128, S_LEN / 128), 256, GM_SMEM>>>(
        hsh, wqkvT, bqkv, qkv, QKV_OUT, HID_);

    // 2) RoPE
    const int total = S_LEN * 72 * HALF_;
    rope_kernel<<<(total + 255) / 256, 256>>>(qkv, cosb, sinb);

    // 3) tensor-core flash attention
    attn_tc<<<dim3(NB_, H_KV_), 256, AT_SMEM>>>(qkv, sinks, attnh);

    // 4) output projection
    gemm_h<<<dim3((HID_ + 127) / 128, S_LEN / 128), 256, GM_SMEM>>>(
        attnh, woT, bo, out, HID_, ATTN_W);
}